// round 16
// baseline (speedup 1.0000x reference)
#include <cuda_runtime.h>
#include <math.h>
#include <stdint.h>

#define D_MODEL  1024
#define N_HEADS  16
#define HEAD_DIM 64
#define BATCH    4
#define SEQ      2048
#define M_TOK    (BATCH * SEQ)   // 8192

// Scratch (allocation-free rule: __device__ globals)
__device__ float    g_qkv[(size_t)M_TOK * 3 * D_MODEL];          // 96 MB; reused as attn A-frag out
__device__ uint32_t g_xpack  [(size_t)M_TOK * D_MODEL * 2];      // x pack, then Q frags
__device__ uint32_t g_attpack[(size_t)M_TOK * D_MODEL * 2];      // K frags
__device__ uint32_t g_vpack  [(size_t)M_TOK * D_MODEL * 2];      // V frags
__device__ uint32_t g_wqkvp  [(size_t)3 * D_MODEL * D_MODEL * 2];
__device__ uint32_t g_woutp  [(size_t)D_MODEL * D_MODEL * 2];
__device__ float2   g_trig[SEQ * 32];                            // (cos,sin) per (t, i)

// ---------------------------------------------------------------------------
__device__ __forceinline__ void cvt_hilo(float f, uint32_t& hi, uint32_t& lo)
{
    asm("cvt.rna.tf32.f32 %0, %1;" : "=r"(hi) : "f"(f));
    float r = f - __uint_as_float(hi);
    asm("cvt.rna.tf32.f32 %0, %1;" : "=r"(lo) : "f"(r));
}

#define MMA_TF32(d, a, b)                                                    \
    asm volatile(                                                            \
        "mma.sync.aligned.m16n8k8.row.col.f32.tf32.tf32.f32 "                \
        "{%0,%1,%2,%3}, {%4,%5,%6,%7}, {%8,%9}, {%0,%1,%2,%3};"              \
        : "+f"(d[0]), "+f"(d[1]), "+f"(d[2]), "+f"(d[3])                     \
        : "r"(a[0]), "r"(a[1]), "r"(a[2]), "r"(a[3]), "r"(b[0]), "r"(b[1]))

__device__ __forceinline__ void cp16(uint32_t saddr, const uint32_t* g)
{
    asm volatile("cp.async.cg.shared.global [%0], [%1], 16;"
                 :: "r"(saddr), "l"(g));
}

// ---------------------------------------------------------------------------
// Trig table: (cos,sin) of fl32(t * fl32(10000^(-i/32))) — matches verified rope.
// ---------------------------------------------------------------------------
__global__ __launch_bounds__(256) void trig_kernel()
{
    int idx = blockIdx.x * 256 + threadIdx.x;   // < SEQ*32
    int i = idx & 31;
    int t = idx >> 5;
    double th = pow(10000.0, -(double)i / 32.0);
    float  f  = (float)t * (float)th;
    double cd, sd;
    sincos((double)f, &cd, &sd);
    g_trig[idx] = make_float2((float)cd, (float)sd);
}

// ---------------------------------------------------------------------------
// GEMM packs (verified R11/R13)
// ---------------------------------------------------------------------------
__global__ __launch_bounds__(256) void pack_a_tf32(
    const float* __restrict__ src, uint32_t* __restrict__ dst)
{
    size_t idx = (size_t)blockIdx.x * 256 + threadIdx.x;
    int row  = (int)(idx >> 8);
    int c4   = (int)(idx & 255) * 4;
    float4 v = *(const float4*)(src + (size_t)row * 1024 + c4);

    int rowTile = row >> 7, rowIn = row & 127;
    int chunk = c4 >> 5, c4in = c4 & 31;
    int mt = rowIn >> 4, ri = rowIn & 15;
    int ks = c4in >> 3;
    int rb = ((ri >> 3) & 1) + (((c4in & 7) >= 4) ? 2 : 0);
    int lb = (ri & 7) * 4;
    size_t base = ((size_t)rowTile * 32 + chunk) * 8192;
    float vv[4] = {v.x, v.y, v.z, v.w};
    #pragma unroll
    for (int j = 0; j < 4; j++) {
        uint32_t hi, lo;
        cvt_hilo(vv[j], hi, lo);
        int off = ((mt * 4 + ks) * 32 + lb + j) * 4 + rb;
        dst[base + off]        = hi;
        dst[base + 4096 + off] = lo;
    }
}

__global__ __launch_bounds__(256) void pack_b_tf32(
    const float* __restrict__ src, uint32_t* __restrict__ dst)
{
    size_t idx = (size_t)blockIdx.x * 256 + threadIdx.x;
    int n   = (int)(idx >> 8);
    int k4  = (int)(idx & 255) * 4;
    float4 v = *(const float4*)(src + (size_t)n * 1024 + k4);

    int nTile = n >> 7, nIn = n & 127;
    int chunk = k4 >> 5, k4in = k4 & 31;
    int nt = nIn >> 3, nin = nIn & 7;
    int ks = k4in >> 3;
    int rg = ((k4in & 7) >= 4) ? 1 : 0;
    size_t base = ((size_t)nTile * 32 + chunk) * 8192;
    float vv[4] = {v.x, v.y, v.z, v.w};
    #pragma unroll
    for (int j = 0; j < 4; j++) {
        uint32_t hi, lo;
        cvt_hilo(vv[j], hi, lo);
        int off = ((nt * 4 + ks) * 32 + nin * 4 + j) * 2 + rg;
        dst[base + off]        = hi;
        dst[base + 4096 + off] = lo;
    }
}

// ---------------------------------------------------------------------------
// TF32 GEMM v3: 3-stage cp.async pipeline, ONE __syncthreads per chunk.
// Order per chunk: wait -> sync -> issue c+2 -> compute c.
// Stage (c+2)%3 held chunk c-1; all warps passed sync => retired. 192KB smem.
// ---------------------------------------------------------------------------
extern __shared__ uint32_t gsm2[];
__global__ __launch_bounds__(256) void gemm_tf32_v2(
    const uint32_t* __restrict__ Apack, const uint32_t* __restrict__ Bpack,
    float* __restrict__ C, int M, int N, int K)
{
    const int tid  = threadIdx.x;
    const int wid  = tid >> 5;
    const int lane = tid & 31;
    const int wm   = wid & 1;
    const int wn   = wid >> 1;
    const int nch  = K >> 5;

    const uint32_t* Asrc = Apack + (size_t)blockIdx.y * nch * 8192;
    const uint32_t* Bsrc = Bpack + (size_t)blockIdx.x * nch * 8192;
    const uint32_t sbase = (uint32_t)__cvta_generic_to_shared(gsm2);

    float acc[4][4][4];
    #pragma unroll
    for (int mt = 0; mt < 4; mt++)
        #pragma unroll
        for (int nt = 0; nt < 4; nt++)
            #pragma unroll
            for (int r = 0; r < 4; r++) acc[mt][nt][r] = 0.f;

    // prologue: chunks 0,1 -> stages 0,1 (two commit groups)
    #pragma unroll
    for (int p = 0; p < 2; p++) {
        uint32_t sb = sbase + p * 65536;
        const uint32_t* As = Asrc + (size_t)p * 8192;
        const uint32_t* Bs = Bsrc + (size_t)p * 8192;
        #pragma unroll
        for (int i = 0; i < 8; i++)
            cp16(sb + (i * 256 + tid) * 16, As + (i * 256 + tid) * 4);
        #pragma unroll
        for (int i = 0; i < 8; i++)
            cp16(sb + 32768 + (i * 256 + tid) * 16, Bs + (i * 256 + tid) * 4);
        asm volatile("cp.async.commit_group;");
    }

    for (int c = 0; c < nch; c++) {
        if (c + 1 < nch)
            asm volatile("cp.async.wait_group 1;" ::: "memory");
        else
            asm volatile("cp.async.wait_group 0;" ::: "memory");
        __syncthreads();   // chunk c visible; all warps retired chunk c-1

        if (c + 2 < nch) {
            uint32_t sb = sbase + ((c + 2) % 3) * 65536;
            const uint32_t* As = Asrc + (size_t)(c + 2) * 8192;
            const uint32_t* Bs = Bsrc + (size_t)(c + 2) * 8192;
            #pragma unroll
            for (int i = 0; i < 8; i++)
                cp16(sb + (i * 256 + tid) * 16, As + (i * 256 + tid) * 4);
            #pragma unroll
            for (int i = 0; i < 8; i++)
                cp16(sb + 32768 + (i * 256 + tid) * 16, Bs + (i * 256 + tid) * 4);
            asm volatile("cp.async.commit_group;");
        }

        const uint32_t* buf = gsm2 + (c % 3) * 16384;
        const uint32_t* AsH = buf;
        const uint32_t* AsL = buf + 4096;
        const uint32_t* BsH = buf + 8192;
        const uint32_t* BsL = buf + 12288;

        #pragma unroll
        for (int ks = 0; ks < 4; ks++) {
            uint32_t bh[4][2], bl[4][2];
            #pragma unroll
            for (int nt = 0; nt < 4; nt++) {
                int off = (((wn * 4 + nt) * 4 + ks) * 32 + lane) * 2;
                uint2 h = *(const uint2*)&BsH[off];
                uint2 l = *(const uint2*)&BsL[off];
                bh[nt][0] = h.x; bh[nt][1] = h.y;
                bl[nt][0] = l.x; bl[nt][1] = l.y;
            }
            #pragma unroll
            for (int mt = 0; mt < 4; mt++) {
                int off = (((wm * 4 + mt) * 4 + ks) * 32 + lane) * 4;
                uint4 h = *(const uint4*)&AsH[off];
                uint4 l = *(const uint4*)&AsL[off];
                uint32_t ah[4] = {h.x, h.y, h.z, h.w};
                uint32_t al[4] = {l.x, l.y, l.z, l.w};
                #pragma unroll
                for (int nt = 0; nt < 4; nt++) {
                    MMA_TF32(acc[mt][nt], ah, bh[nt]);
                    MMA_TF32(acc[mt][nt], al, bh[nt]);
                    MMA_TF32(acc[mt][nt], ah, bl[nt]);
                }
            }
        }
    }

    const size_t arow0 = (size_t)blockIdx.y * 128;
    const size_t brow0 = (size_t)blockIdx.x * 128;
    #pragma unroll
    for (int mt = 0; mt < 4; mt++) {
        size_t row = arow0 + wm * 64 + mt * 16 + (lane >> 2);
        #pragma unroll
        for (int nt = 0; nt < 4; nt++) {
            size_t col = brow0 + wn * 32 + nt * 8 + (lane & 3) * 2;
            *(float2*)(C + row * N + col) =
                make_float2(acc[mt][nt][0], acc[mt][nt][1]);
            *(float2*)(C + (row + 8) * N + col) =
                make_float2(acc[mt][nt][2], acc[mt][nt][3]);
        }
    }
}

// ---------------------------------------------------------------------------
// Fused RoPE + Q/K/V fragment pack (verified R15).
// ---------------------------------------------------------------------------
extern __shared__ float rps[];
__global__ __launch_bounds__(256) void rope_pack(
    uint32_t* __restrict__ Qp, uint32_t* __restrict__ Kp,
    uint32_t* __restrict__ Vp)
{
    const int tid  = threadIdx.x;
    const int wid  = tid >> 5;
    const int lane = tid & 31;
    const int qt   = blockIdx.x;
    const int bh   = blockIdx.y;
    const int b    = bh >> 4;
    const int h    = bh & 15;
    const int t0   = qt * 128;
    const size_t tok0 = (size_t)b * SEQ + t0;

    float* Qs = rps;
    float* Ks = rps + 128 * 68;
    float* Vs = rps + 2 * 128 * 68;

    #pragma unroll
    for (int mat = 0; mat < 3; mat++) {
        float* dst = rps + mat * 128 * 68;
        const float* src = g_qkv + tok0 * 3072 + mat * 1024 + h * 64;
        #pragma unroll
        for (int i = 0; i < 8; i++) {
            int idx = tid + i * 256;
            int r   = idx >> 4;
            int d4  = (idx & 15) * 4;
            *(float4*)&dst[r * 68 + d4] = *(const float4*)(src + (size_t)r * 3072 + d4);
        }
    }
    __syncthreads();

    #pragma unroll
    for (int i = 0; i < 16; i++) {
        int idx = tid + i * 256;
        int r   = idx >> 5;
        int fi  = idx & 31;
        float2 cs = g_trig[(t0 + r) * 32 + fi];
        float x1 = Qs[r * 68 + fi], x2 = Qs[r * 68 + fi + 32];
        Qs[r * 68 + fi]      = x1 * cs.x + x2 * cs.y;
        Qs[r * 68 + fi + 32] = x2 * cs.x - x1 * cs.y;
        float y1 = Ks[r * 68 + fi], y2 = Ks[r * 68 + fi + 32];
        Ks[r * 68 + fi]      = y1 * cs.x + y2 * cs.y;
        Ks[r * 68 + fi + 32] = y2 * cs.x - y1 * cs.y;
    }
    __syncthreads();

    {
        uint32_t* base = Qp + ((size_t)bh * 16 + qt) * 16384;
        int mt = wid;
        #pragma unroll
        for (int ks = 0; ks < 8; ks++) {
            uint32_t hi[4], lo[4];
            #pragma unroll
            for (int r = 0; r < 4; r++) {
                int ri = (lane >> 2) + 8 * (r & 1);
                int k  = ks * 8 + (lane & 3) + 4 * (r >> 1);
                cvt_hilo(Qs[(mt * 16 + ri) * 68 + k], hi[r], lo[r]);
            }
            int word = (mt * 8 + ks) * 128 + lane * 4;
            *(uint4*)(base + word)        = make_uint4(hi[0], hi[1], hi[2], hi[3]);
            *(uint4*)(base + 8192 + word) = make_uint4(lo[0], lo[1], lo[2], lo[3]);
        }
    }

    #pragma unroll
    for (int half = 0; half < 2; half++) {
        int kt = qt * 2 + half;
        size_t basei = ((size_t)bh * 32 + kt) * 8192;
        int nt = wid;
        #pragma unroll
        for (int ks = 0; ks < 8; ks++) {
            uint32_t khi[2], klo[2], vhi[2], vlo[2];
            #pragma unroll
            for (int r = 0; r < 2; r++) {
                int c = half * 64 + nt * 8 + (lane >> 2);
                int k = ks * 8 + (lane & 3) + 4 * r;
                cvt_hilo(Ks[c * 68 + k], khi[r], klo[r]);
                int d  = nt * 8 + (lane >> 2);
                int c2 = half * 64 + ks * 8 + (lane & 3) + 4 * r;
                cvt_hilo(Vs[c2 * 68 + d], vhi[r], vlo[r]);
            }
            int word = (nt * 8 + ks) * 64 + lane * 2;
            *(uint2*)(Kp + basei + word)        = make_uint2(khi[0], khi[1]);
            *(uint2*)(Kp + basei + 4096 + word) = make_uint2(klo[0], klo[1]);
            *(uint2*)(Vp + basei + word)        = make_uint2(vhi[0], vhi[1]);
            *(uint2*)(Vp + basei + 4096 + word) = make_uint2(vlo[0], vlo[1]);
        }
    }
}

// ---------------------------------------------------------------------------
// Tensor-core flash attention (verified R14/R15 math), ONE sync per chunk:
// wait -> sync -> issue c+1 -> compute c. Buffer (c+1)&1 held chunk c-1,
// retired by the sync. Epilogue writes out-proj A-frags directly.
// ---------------------------------------------------------------------------
extern __shared__ uint32_t atsm[];
__global__ __launch_bounds__(256) void attn_tc(
    const uint32_t* __restrict__ Qp, const uint32_t* __restrict__ Kp,
    const uint32_t* __restrict__ Vp, uint32_t* __restrict__ Ap)
{
    const int tid  = threadIdx.x;
    const int wid  = tid >> 5;
    const int lane = tid & 31;
    const int bx   = gridDim.x - 1 - blockIdx.x;
    const int bh   = blockIdx.y;
    const int b    = bh >> 4;
    const int h    = bh & 15;
    const int q0   = bx * 128;
    const int nch  = 2 * (bx + 1);

    const uint32_t sbase = (uint32_t)__cvta_generic_to_shared(atsm);
    const uint32_t* Qsrc = Qp + ((size_t)bh * 16 + bx) * 16384;
    const uint32_t* Ksrc = Kp + (size_t)bh * 32 * 8192;
    const uint32_t* Vsrc = Vp + (size_t)bh * 32 * 8192;

    // prologue: Q + chunk0 K,V (one commit group)
    #pragma unroll
    for (int i = 0; i < 16; i++)
        cp16(sbase + (i * 256 + tid) * 16, Qsrc + (i * 256 + tid) * 4);
    #pragma unroll
    for (int i = 0; i < 8; i++)
        cp16(sbase + 65536 + (i * 256 + tid) * 16, Ksrc + (i * 256 + tid) * 4);
    #pragma unroll
    for (int i = 0; i < 8; i++)
        cp16(sbase + 65536 + 32768 + (i * 256 + tid) * 16, Vsrc + (i * 256 + tid) * 4);
    asm volatile("cp.async.commit_group;");

    float o[8][4];
    #pragma unroll
    for (int nt = 0; nt < 8; nt++)
        #pragma unroll
        for (int j = 0; j < 4; j++) o[nt][j] = 0.f;
    float m0 = -1e30f, m1 = -1e30f, l0 = 0.f, l1 = 0.f;

    const int row0 = q0 + wid * 16 + (lane >> 2);
    const int c4l  = lane & 31 & 3;
    const int idx1 = (lane & 28) | (c4l >> 1);
    const int idx2 = idx1 + 2;

    for (int c = 0; c < nch; c++) {
        asm volatile("cp.async.wait_group 0;" ::: "memory");
        __syncthreads();   // chunk c visible; chunk c-1 retired by all warps

        if (c + 1 < nch) {
            uint32_t sb = sbase + 65536 + ((c + 1) & 1) * 65536;
            const uint32_t* Ks = Ksrc + (size_t)(c + 1) * 8192;
            const uint32_t* Vs = Vsrc + (size_t)(c + 1) * 8192;
            #pragma unroll
            for (int i = 0; i < 8; i++)
                cp16(sb + (i * 256 + tid) * 16, Ks + (i * 256 + tid) * 4);
            #pragma unroll
            for (int i = 0; i < 8; i++)
                cp16(sb + 32768 + (i * 256 + tid) * 16, Vs + (i * 256 + tid) * 4);
            asm volatile("cp.async.commit_group;");
        }

        const uint32_t* QF = atsm;
        const uint32_t* KF = atsm + 16384 + (c & 1) * 16384;
        const uint32_t* VF = KF + 8192;

        float s[8][4];
        #pragma unroll
        for (int nt = 0; nt < 8; nt++)
            #pragma unroll
            for (int j = 0; j < 4; j++) s[nt][j] = 0.f;

        #pragma unroll
        for (int ks = 0; ks < 8; ks++) {
            uint4 qh4 = *(const uint4*)&QF[(wid * 8 + ks) * 128 + lane * 4];
            uint4 ql4 = *(const uint4*)&QF[8192 + (wid * 8 + ks) * 128 + lane * 4];
            uint32_t qh[4] = {qh4.x, qh4.y, qh4.z, qh4.w};
            uint32_t ql[4] = {ql4.x, ql4.y, ql4.z, ql4.w};
            #pragma unroll
            for (int nt = 0; nt < 8; nt++) {
                uint2 kh2 = *(const uint2*)&KF[(nt * 8 + ks) * 64 + lane * 2];
                uint2 kl2 = *(const uint2*)&KF[4096 + (nt * 8 + ks) * 64 + lane * 2];
                uint32_t kh[2] = {kh2.x, kh2.y};
                uint32_t kl[2] = {kl2.x, kl2.y};
                MMA_TF32(s[nt], qh, kh);
                MMA_TF32(s[nt], ql, kh);
                MMA_TF32(s[nt], qh, kl);
            }
        }

        const int j0 = c * 64;
        if (c >= 2 * bx) {
            #pragma unroll
            for (int nt = 0; nt < 8; nt++) {
                #pragma unroll
                for (int j = 0; j < 4; j++) {
                    int col = j0 + nt * 8 + c4l * 2 + (j & 1);
                    int row = (j < 2) ? row0 : row0 + 8;
                    s[nt][j] = (col <= row) ? s[nt][j] * 0.125f : -1e30f;
                }
            }
        } else {
            #pragma unroll
            for (int nt = 0; nt < 8; nt++)
                #pragma unroll
                for (int j = 0; j < 4; j++) s[nt][j] *= 0.125f;
        }

        float mt0 = -1e30f, mt1 = -1e30f;
        #pragma unroll
        for (int nt = 0; nt < 8; nt++) {
            mt0 = fmaxf(mt0, fmaxf(s[nt][0], s[nt][1]));
            mt1 = fmaxf(mt1, fmaxf(s[nt][2], s[nt][3]));
        }
        mt0 = fmaxf(mt0, __shfl_xor_sync(0xffffffffu, mt0, 1));
        mt0 = fmaxf(mt0, __shfl_xor_sync(0xffffffffu, mt0, 2));
        mt1 = fmaxf(mt1, __shfl_xor_sync(0xffffffffu, mt1, 1));
        mt1 = fmaxf(mt1, __shfl_xor_sync(0xffffffffu, mt1, 2));

        float m0n = fmaxf(m0, mt0), m1n = fmaxf(m1, mt1);
        float a0 = __expf(m0 - m0n), a1 = __expf(m1 - m1n);
        m0 = m0n; m1 = m1n;

        float lt0 = 0.f, lt1 = 0.f;
        #pragma unroll
        for (int nt = 0; nt < 8; nt++) {
            s[nt][0] = __expf(s[nt][0] - m0n);
            s[nt][1] = __expf(s[nt][1] - m0n);
            s[nt][2] = __expf(s[nt][2] - m1n);
            s[nt][3] = __expf(s[nt][3] - m1n);
            lt0 += s[nt][0] + s[nt][1];
            lt1 += s[nt][2] + s[nt][3];
        }
        lt0 += __shfl_xor_sync(0xffffffffu, lt0, 1);
        lt0 += __shfl_xor_sync(0xffffffffu, lt0, 2);
        lt1 += __shfl_xor_sync(0xffffffffu, lt1, 1);
        lt1 += __shfl_xor_sync(0xffffffffu, lt1, 2);
        l0 = l0 * a0 + lt0;
        l1 = l1 * a1 + lt1;

        #pragma unroll
        for (int nt = 0; nt < 8; nt++) {
            o[nt][0] *= a0; o[nt][1] *= a0;
            o[nt][2] *= a1; o[nt][3] *= a1;
        }

        #pragma unroll
        for (int ks2 = 0; ks2 < 8; ks2++) {
            float v0a = __shfl_sync(0xffffffffu, s[ks2][0], idx1);
            float v0b = __shfl_sync(0xffffffffu, s[ks2][1], idx1);
            float v2a = __shfl_sync(0xffffffffu, s[ks2][0], idx2);
            float v2b = __shfl_sync(0xffffffffu, s[ks2][1], idx2);
            float v1a = __shfl_sync(0xffffffffu, s[ks2][2], idx1);
            float v1b = __shfl_sync(0xffffffffu, s[ks2][3], idx1);
            float v3a = __shfl_sync(0xffffffffu, s[ks2][2], idx2);
            float v3b = __shfl_sync(0xffffffffu, s[ks2][3], idx2);
            bool oddc = (c4l & 1);
            float af0 = oddc ? v0b : v0a;
            float af1 = oddc ? v1b : v1a;
            float af2 = oddc ? v2b : v2a;
            float af3 = oddc ? v3b : v3a;

            uint32_t pah[4], pal[4];
            cvt_hilo(af0, pah[0], pal[0]);
            cvt_hilo(af1, pah[1], pal[1]);
            cvt_hilo(af2, pah[2], pal[2]);
            cvt_hilo(af3, pah[3], pal[3]);

            #pragma unroll
            for (int nt = 0; nt < 8; nt++) {
                uint2 vh2 = *(const uint2*)&VF[(nt * 8 + ks2) * 64 + lane * 2];
                uint2 vl2 = *(const uint2*)&VF[4096 + (nt * 8 + ks2) * 64 + lane * 2];
                uint32_t vh[2] = {vh2.x, vh2.y};
                uint32_t vl[2] = {vl2.x, vl2.y};
                MMA_TF32(o[nt], pah, vh);
                MMA_TF32(o[nt], pal, vh);
                MMA_TF32(o[nt], pah, vl);
            }
        }
    }

    // epilogue: normalize, acc->A-frag shuffle, store packed
    float inv0 = 1.0f / l0, inv1 = 1.0f / l1;
    #pragma unroll
    for (int nt = 0; nt < 8; nt++) {
        float n0 = o[nt][0] * inv0, n1 = o[nt][1] * inv0;
        float n2 = o[nt][2] * inv1, n3 = o[nt][3] * inv1;

        float v0a = __shfl_sync(0xffffffffu, n0, idx1);
        float v0b = __shfl_sync(0xffffffffu, n1, idx1);
        float v2a = __shfl_sync(0xffffffffu, n0, idx2);
        float v2b = __shfl_sync(0xffffffffu, n1, idx2);
        float v1a = __shfl_sync(0xffffffffu, n2, idx1);
        float v1b = __shfl_sync(0xffffffffu, n3, idx1);
        float v3a = __shfl_sync(0xffffffffu, n2, idx2);
        float v3b = __shfl_sync(0xffffffffu, n3, idx2);
        bool oddc = (c4l & 1);
        float af0 = oddc ? v0b : v0a;
        float af1 = oddc ? v1b : v1a;
        float af2 = oddc ? v2b : v2a;
        float af3 = oddc ? v3b : v3a;

        uint32_t hi[4], lo[4];
        cvt_hilo(af0, hi[0], lo[0]);
        cvt_hilo(af1, hi[1], lo[1]);
        cvt_hilo(af2, hi[2], lo[2]);
        cvt_hilo(af3, hi[3], lo[3]);

        size_t base = ((size_t)(b * 16 + bx) * 32 + h * 2 + (nt >> 2)) * 8192;
        int word = ((wid * 4 + (nt & 3)) * 32 + lane) * 4;
        *(uint4*)(Ap + base + word)        = make_uint4(hi[0], hi[1], hi[2], hi[3]);
        *(uint4*)(Ap + base + 4096 + word) = make_uint4(lo[0], lo[1], lo[2], lo[3]);
    }
}

// ---------------------------------------------------------------------------
extern "C" void kernel_launch(void* const* d_in, const int* in_sizes, int n_in,
                              void* d_out, int out_size)
{
    const float* x     = (const float*)d_in[0];
    const float* w_qkv = (const float*)d_in[1];
    const float* w_out = (const float*)d_in[2];
    for (int i = 0; i < n_in; i++) {
        if      (in_sizes[i] == M_TOK * D_MODEL)       x     = (const float*)d_in[i];
        else if (in_sizes[i] == 3 * D_MODEL * D_MODEL) w_qkv = (const float*)d_in[i];
        else if (in_sizes[i] == D_MODEL * D_MODEL)     w_out = (const float*)d_in[i];
    }
    float* out = (float*)d_out;

    float *qkv = nullptr;
    uint32_t *xp = nullptr, *ap = nullptr, *vp = nullptr, *wqp = nullptr, *wop = nullptr;
    cudaGetSymbolAddress((void**)&qkv, g_qkv);
    cudaGetSymbolAddress((void**)&xp,  g_xpack);
    cudaGetSymbolAddress((void**)&ap,  g_attpack);
    cudaGetSymbolAddress((void**)&vp,  g_vpack);
    cudaGetSymbolAddress((void**)&wqp, g_wqkvp);
    cudaGetSymbolAddress((void**)&wop, g_woutp);

    static bool attr_set = false;
    if (!attr_set) {
        attr_set = true;
        cudaFuncSetAttribute(gemm_tf32_v2,
                             cudaFuncAttributeMaxDynamicSharedMemorySize, 192 * 1024);
        cudaFuncSetAttribute(attn_tc,
                             cudaFuncAttributeMaxDynamicSharedMemorySize, 192 * 1024);
        cudaFuncSetAttribute(rope_pack,
                             cudaFuncAttributeMaxDynamicSharedMemorySize, 112 * 1024);
    }

    // 0) trig table + GEMM operand packs
    trig_kernel<<<(SEQ * 32) / 256, 256>>>();
    pack_a_tf32<<<(M_TOK * 1024 / 4) / 256, 256>>>(x, xp);
    pack_b_tf32<<<(3 * D_MODEL * 1024 / 4) / 256, 256>>>(w_qkv, wqp);
    pack_b_tf32<<<(D_MODEL * 1024 / 4) / 256, 256>>>(w_out, wop);

    // 1) QKV projection -> g_qkv
    gemm_tf32_v2<<<dim3(3 * D_MODEL / 128, M_TOK / 128), 256, 192 * 1024>>>(
        xp, wqp, qkv, M_TOK, 3 * D_MODEL, D_MODEL);

    // 2) Fused rope + Q/K/V fragment pack
    rope_pack<<<dim3(16, 64), 256, 112 * 1024>>>(xp, ap, vp);

    // 3) Tensor-core flash attention; epilogue emits out-proj A-frags into g_qkv
    attn_tc<<<dim3(SEQ / 128, BATCH * N_HEADS), 256, 192 * 1024>>>(
        xp, ap, vp, (uint32_t*)qkv);

    // 4) Output projection (reads A-frags from g_qkv)
    gemm_tf32_v2<<<dim3(D_MODEL / 128, M_TOK / 128), 256, 192 * 1024>>>(
        (const uint32_t*)qkv, wop, out, M_TOK, D_MODEL, D_MODEL);
}

// round 17
// speedup vs baseline: 1.4535x; 1.4535x over previous
#include <cuda_runtime.h>
#include <cuda_bf16.h>
#include <math.h>
#include <stdint.h>

#define D_MODEL  1024
#define N_HEADS  16
#define HEAD_DIM 64
#define BATCH    4
#define SEQ      2048
#define M_TOK    (BATCH * SEQ)   // 8192

// Scratch (allocation-free rule: __device__ globals)
__device__ float    g_qkv[(size_t)M_TOK * 3 * D_MODEL];          // QKV floats; reused as bf16 A-frags for out-proj
__device__ uint32_t g_xpack  [(size_t)M_TOK * D_MODEL * 2];      // x bf16-pack, then tf32 Q frags
__device__ uint32_t g_attpack[(size_t)M_TOK * D_MODEL * 2];      // tf32 K frags
__device__ uint32_t g_vpack  [(size_t)M_TOK * D_MODEL * 2];      // tf32 V frags
__device__ uint32_t g_wqkvp  [(size_t)3 * D_MODEL * D_MODEL * 2];
__device__ uint32_t g_woutp  [(size_t)D_MODEL * D_MODEL * 2];
__device__ float2   g_trig[SEQ * 32];

// ---------------------------------------------------------------------------
__device__ __forceinline__ void cvt_hilo(float f, uint32_t& hi, uint32_t& lo)
{
    asm("cvt.rna.tf32.f32 %0, %1;" : "=r"(hi) : "f"(f));
    float r = f - __uint_as_float(hi);
    asm("cvt.rna.tf32.f32 %0, %1;" : "=r"(lo) : "f"(r));
}

// pack two floats into bf16x2 hi and lo-residual bf16x2
__device__ __forceinline__ void bf16_hilo2(float x0, float x1,
                                           uint32_t& hi, uint32_t& lo)
{
    __nv_bfloat16 h0 = __float2bfloat16(x0);
    __nv_bfloat16 h1 = __float2bfloat16(x1);
    float r0 = x0 - __bfloat162float(h0);
    float r1 = x1 - __bfloat162float(h1);
    __nv_bfloat16 l0 = __float2bfloat16(r0);
    __nv_bfloat16 l1 = __float2bfloat16(r1);
    hi = ((uint32_t)__bfloat16_as_ushort(h1) << 16) | __bfloat16_as_ushort(h0);
    lo = ((uint32_t)__bfloat16_as_ushort(l1) << 16) | __bfloat16_as_ushort(l0);
}

#define MMA_TF32(d, a, b)                                                    \
    asm volatile(                                                            \
        "mma.sync.aligned.m16n8k8.row.col.f32.tf32.tf32.f32 "                \
        "{%0,%1,%2,%3}, {%4,%5,%6,%7}, {%8,%9}, {%0,%1,%2,%3};"              \
        : "+f"(d[0]), "+f"(d[1]), "+f"(d[2]), "+f"(d[3])                     \
        : "r"(a[0]), "r"(a[1]), "r"(a[2]), "r"(a[3]), "r"(b[0]), "r"(b[1]))

#define MMA_BF16(d, a, b)                                                    \
    asm volatile(                                                            \
        "mma.sync.aligned.m16n8k16.row.col.f32.bf16.bf16.f32 "               \
        "{%0,%1,%2,%3}, {%4,%5,%6,%7}, {%8,%9}, {%0,%1,%2,%3};"              \
        : "+f"(d[0]), "+f"(d[1]), "+f"(d[2]), "+f"(d[3])                     \
        : "r"(a[0]), "r"(a[1]), "r"(a[2]), "r"(a[3]), "r"(b[0]), "r"(b[1]))

__device__ __forceinline__ void cp16(uint32_t saddr, const uint32_t* g)
{
    asm volatile("cp.async.cg.shared.global [%0], [%1], 16;"
                 :: "r"(saddr), "l"(g));
}

// ---------------------------------------------------------------------------
__global__ __launch_bounds__(256) void trig_kernel()
{
    int idx = blockIdx.x * 256 + threadIdx.x;
    int i = idx & 31;
    int t = idx >> 5;
    double th = pow(10000.0, -(double)i / 32.0);
    float  f  = (float)t * (float)th;
    double cd, sd;
    sincos((double)f, &cd, &sd);
    g_trig[idx] = make_float2((float)cd, (float)sd);
}

// ---------------------------------------------------------------------------
// BF16 GEMM packs. Layout per 128-row tile: 32 chunks (BK=32) of 4096 u32
// (hi [0,2048), lo [2048,4096)).
// A-frag (m16n8k16): off = ((mt*2+ks)*32+lane)*4 + reg
//   row = mt*16 + (lane>>2) + 8*(reg&1); k = ks*16 + (lane&3)*2 + 8*(reg>>1) (+0,1)
// B-frag: off = ((nt*2+ks)*32+lane)*2 + reg
//   n = nt*8 + (lane>>2); k = ks*16 + (lane&3)*2 + 8*reg (+0,1)
// ---------------------------------------------------------------------------
__global__ __launch_bounds__(256) void pack_a_bf16(
    const float* __restrict__ src, uint32_t* __restrict__ dst)
{
    size_t idx = (size_t)blockIdx.x * 256 + threadIdx.x;
    int reg   = (int)(idx & 3);
    int lane  = (int)(idx >> 2) & 31;
    int ks    = (int)(idx >> 7) & 1;
    int mt    = (int)(idx >> 8) & 7;
    int chunk = (int)(idx >> 11) & 31;
    int tile  = (int)(idx >> 16);

    int row = tile * 128 + mt * 16 + (lane >> 2) + 8 * (reg & 1);
    int k   = chunk * 32 + ks * 16 + (lane & 3) * 2 + 8 * (reg >> 1);
    float2 v = *(const float2*)(src + (size_t)row * 1024 + k);

    uint32_t hi, lo;
    bf16_hilo2(v.x, v.y, hi, lo);
    size_t base = (size_t)tile * 131072 + (size_t)chunk * 4096;
    int off = ((mt * 2 + ks) * 32 + lane) * 4 + reg;
    dst[base + off]        = hi;
    dst[base + 2048 + off] = lo;
}

__global__ __launch_bounds__(256) void pack_b_bf16(
    const float* __restrict__ src, uint32_t* __restrict__ dst)
{
    size_t idx = (size_t)blockIdx.x * 256 + threadIdx.x;
    int reg   = (int)(idx & 1);
    int lane  = (int)(idx >> 1) & 31;
    int ks    = (int)(idx >> 6) & 1;
    int nt    = (int)(idx >> 7) & 15;
    int chunk = (int)(idx >> 11) & 31;
    int tile  = (int)(idx >> 16);

    int n = tile * 128 + nt * 8 + (lane >> 2);
    int k = chunk * 32 + ks * 16 + (lane & 3) * 2 + 8 * reg;
    float2 v = *(const float2*)(src + (size_t)n * 1024 + k);

    uint32_t hi, lo;
    bf16_hilo2(v.x, v.y, hi, lo);
    size_t base = (size_t)tile * 131072 + (size_t)chunk * 4096;
    int off = ((nt * 2 + ks) * 32 + lane) * 2 + reg;
    dst[base + off]        = hi;
    dst[base + 2048 + off] = lo;
}

// ---------------------------------------------------------------------------
// BF16 GEMM (3-pass hi/lo): C[M,N] = A @ W^T. Tiles 128x128, BK=32, 256 thr,
// warp grid 2x4, warp tile 64x32. 2-stage cp.async (32KB/chunk, 64KB smem).
// Control flow = verified R13 skeleton.
// ---------------------------------------------------------------------------
extern __shared__ uint32_t gsm2[];
__global__ __launch_bounds__(256) void gemm_bf16(
    const uint32_t* __restrict__ Apack, const uint32_t* __restrict__ Bpack,
    float* __restrict__ C, int M, int N, int K)
{
    const int tid  = threadIdx.x;
    const int wid  = tid >> 5;
    const int lane = tid & 31;
    const int wm   = wid & 1;
    const int wn   = wid >> 1;
    const int nch  = K >> 5;   // 32

    const uint32_t* Asrc = Apack + (size_t)blockIdx.y * nch * 4096;
    const uint32_t* Bsrc = Bpack + (size_t)blockIdx.x * nch * 4096;
    const uint32_t sbase = (uint32_t)__cvta_generic_to_shared(gsm2);

    float acc[4][4][4];
    #pragma unroll
    for (int mt = 0; mt < 4; mt++)
        #pragma unroll
        for (int nt = 0; nt < 4; nt++)
            #pragma unroll
            for (int r = 0; r < 4; r++) acc[mt][nt][r] = 0.f;

    // stage chunk 0 into buf 0 (A 4096 u32, then B 4096 u32)
    {
        #pragma unroll
        for (int i = 0; i < 4; i++)
            cp16(sbase + (i * 256 + tid) * 16, Asrc + (i * 256 + tid) * 4);
        #pragma unroll
        for (int i = 0; i < 4; i++)
            cp16(sbase + 16384 + (i * 256 + tid) * 16, Bsrc + (i * 256 + tid) * 4);
        asm volatile("cp.async.commit_group;");
    }

    for (int c = 0; c < nch; c++) {
        __syncthreads();
        if (c + 1 < nch) {
            uint32_t sb = sbase + ((c + 1) & 1) * 32768;
            const uint32_t* As = Asrc + (size_t)(c + 1) * 4096;
            const uint32_t* Bs = Bsrc + (size_t)(c + 1) * 4096;
            #pragma unroll
            for (int i = 0; i < 4; i++)
                cp16(sb + (i * 256 + tid) * 16, As + (i * 256 + tid) * 4);
            #pragma unroll
            for (int i = 0; i < 4; i++)
                cp16(sb + 16384 + (i * 256 + tid) * 16, Bs + (i * 256 + tid) * 4);
            asm volatile("cp.async.commit_group;");
            asm volatile("cp.async.wait_group 1;" ::: "memory");
        } else {
            asm volatile("cp.async.wait_group 0;" ::: "memory");
        }
        __syncthreads();

        const uint32_t* buf = gsm2 + (c & 1) * 8192;
        const uint32_t* AsH = buf;
        const uint32_t* AsL = buf + 2048;
        const uint32_t* BsH = buf + 4096;
        const uint32_t* BsL = buf + 6144;

        #pragma unroll
        for (int ks = 0; ks < 2; ks++) {
            uint32_t bh[4][2], bl[4][2];
            #pragma unroll
            for (int nt = 0; nt < 4; nt++) {
                int off = (((wn * 4 + nt) * 2 + ks) * 32 + lane) * 2;
                uint2 h = *(const uint2*)&BsH[off];
                uint2 l = *(const uint2*)&BsL[off];
                bh[nt][0] = h.x; bh[nt][1] = h.y;
                bl[nt][0] = l.x; bl[nt][1] = l.y;
            }
            #pragma unroll
            for (int mt = 0; mt < 4; mt++) {
                int off = (((wm * 4 + mt) * 2 + ks) * 32 + lane) * 4;
                uint4 h = *(const uint4*)&AsH[off];
                uint4 l = *(const uint4*)&AsL[off];
                uint32_t ah[4] = {h.x, h.y, h.z, h.w};
                uint32_t al[4] = {l.x, l.y, l.z, l.w};
                #pragma unroll
                for (int nt = 0; nt < 4; nt++) {
                    MMA_BF16(acc[mt][nt], ah, bh[nt]);
                    MMA_BF16(acc[mt][nt], al, bh[nt]);
                    MMA_BF16(acc[mt][nt], ah, bl[nt]);
                }
            }
        }
    }

    const size_t arow0 = (size_t)blockIdx.y * 128;
    const size_t brow0 = (size_t)blockIdx.x * 128;
    #pragma unroll
    for (int mt = 0; mt < 4; mt++) {
        size_t row = arow0 + wm * 64 + mt * 16 + (lane >> 2);
        #pragma unroll
        for (int nt = 0; nt < 4; nt++) {
            size_t col = brow0 + wn * 32 + nt * 8 + (lane & 3) * 2;
            *(float2*)(C + row * N + col) =
                make_float2(acc[mt][nt][0], acc[mt][nt][1]);
            *(float2*)(C + (row + 8) * N + col) =
                make_float2(acc[mt][nt][2], acc[mt][nt][3]);
        }
    }
}

// ---------------------------------------------------------------------------
// Fused RoPE + tf32 Q/K/V fragment pack (verified R15). Unchanged.
// ---------------------------------------------------------------------------
extern __shared__ float rps[];
__global__ __launch_bounds__(256) void rope_pack(
    uint32_t* __restrict__ Qp, uint32_t* __restrict__ Kp,
    uint32_t* __restrict__ Vp)
{
    const int tid  = threadIdx.x;
    const int wid  = tid >> 5;
    const int lane = tid & 31;
    const int qt   = blockIdx.x;
    const int bh   = blockIdx.y;
    const int b    = bh >> 4;
    const int h    = bh & 15;
    const int t0   = qt * 128;
    const size_t tok0 = (size_t)b * SEQ + t0;

    float* Qs = rps;
    float* Ks = rps + 128 * 68;
    float* Vs = rps + 2 * 128 * 68;

    #pragma unroll
    for (int mat = 0; mat < 3; mat++) {
        float* dst = rps + mat * 128 * 68;
        const float* src = g_qkv + tok0 * 3072 + mat * 1024 + h * 64;
        #pragma unroll
        for (int i = 0; i < 8; i++) {
            int idx = tid + i * 256;
            int r   = idx >> 4;
            int d4  = (idx & 15) * 4;
            *(float4*)&dst[r * 68 + d4] = *(const float4*)(src + (size_t)r * 3072 + d4);
        }
    }
    __syncthreads();

    #pragma unroll
    for (int i = 0; i < 16; i++) {
        int idx = tid + i * 256;
        int r   = idx >> 5;
        int fi  = idx & 31;
        float2 cs = g_trig[(t0 + r) * 32 + fi];
        float x1 = Qs[r * 68 + fi], x2 = Qs[r * 68 + fi + 32];
        Qs[r * 68 + fi]      = x1 * cs.x + x2 * cs.y;
        Qs[r * 68 + fi + 32] = x2 * cs.x - x1 * cs.y;
        float y1 = Ks[r * 68 + fi], y2 = Ks[r * 68 + fi + 32];
        Ks[r * 68 + fi]      = y1 * cs.x + y2 * cs.y;
        Ks[r * 68 + fi + 32] = y2 * cs.x - y1 * cs.y;
    }
    __syncthreads();

    {
        uint32_t* base = Qp + ((size_t)bh * 16 + qt) * 16384;
        int mt = wid;
        #pragma unroll
        for (int ks = 0; ks < 8; ks++) {
            uint32_t hi[4], lo[4];
            #pragma unroll
            for (int r = 0; r < 4; r++) {
                int ri = (lane >> 2) + 8 * (r & 1);
                int k  = ks * 8 + (lane & 3) + 4 * (r >> 1);
                cvt_hilo(Qs[(mt * 16 + ri) * 68 + k], hi[r], lo[r]);
            }
            int word = (mt * 8 + ks) * 128 + lane * 4;
            *(uint4*)(base + word)        = make_uint4(hi[0], hi[1], hi[2], hi[3]);
            *(uint4*)(base + 8192 + word) = make_uint4(lo[0], lo[1], lo[2], lo[3]);
        }
    }

    #pragma unroll
    for (int half = 0; half < 2; half++) {
        int kt = qt * 2 + half;
        size_t basei = ((size_t)bh * 32 + kt) * 8192;
        int nt = wid;
        #pragma unroll
        for (int ks = 0; ks < 8; ks++) {
            uint32_t khi[2], klo[2], vhi[2], vlo[2];
            #pragma unroll
            for (int r = 0; r < 2; r++) {
                int c = half * 64 + nt * 8 + (lane >> 2);
                int k = ks * 8 + (lane & 3) + 4 * r;
                cvt_hilo(Ks[c * 68 + k], khi[r], klo[r]);
                int d  = nt * 8 + (lane >> 2);
                int c2 = half * 64 + ks * 8 + (lane & 3) + 4 * r;
                cvt_hilo(Vs[c2 * 68 + d], vhi[r], vlo[r]);
            }
            int word = (nt * 8 + ks) * 64 + lane * 2;
            *(uint2*)(Kp + basei + word)        = make_uint2(khi[0], khi[1]);
            *(uint2*)(Kp + basei + 4096 + word) = make_uint2(klo[0], klo[1]);
            *(uint2*)(Vp + basei + word)        = make_uint2(vhi[0], vhi[1]);
            *(uint2*)(Vp + basei + 4096 + word) = make_uint2(vlo[0], vlo[1]);
        }
    }
}

// ---------------------------------------------------------------------------
// Tensor-core flash attention (tf32, verified R14/R16). Epilogue now writes
// bf16 out-proj A-frags DIRECTLY (acc pairs map 1:1 to k16 A-frag regs).
// ---------------------------------------------------------------------------
extern __shared__ uint32_t atsm[];
__global__ __launch_bounds__(256) void attn_tc(
    const uint32_t* __restrict__ Qp, const uint32_t* __restrict__ Kp,
    const uint32_t* __restrict__ Vp, uint32_t* __restrict__ Ap)
{
    const int tid  = threadIdx.x;
    const int wid  = tid >> 5;
    const int lane = tid & 31;
    const int bx   = gridDim.x - 1 - blockIdx.x;
    const int bh   = blockIdx.y;
    const int b    = bh >> 4;
    const int h    = bh & 15;
    const int q0   = bx * 128;
    const int nch  = 2 * (bx + 1);

    const uint32_t sbase = (uint32_t)__cvta_generic_to_shared(atsm);
    const uint32_t* Qsrc = Qp + ((size_t)bh * 16 + bx) * 16384;
    const uint32_t* Ksrc = Kp + (size_t)bh * 32 * 8192;
    const uint32_t* Vsrc = Vp + (size_t)bh * 32 * 8192;

    #pragma unroll
    for (int i = 0; i < 16; i++)
        cp16(sbase + (i * 256 + tid) * 16, Qsrc + (i * 256 + tid) * 4);
    #pragma unroll
    for (int i = 0; i < 8; i++)
        cp16(sbase + 65536 + (i * 256 + tid) * 16, Ksrc + (i * 256 + tid) * 4);
    #pragma unroll
    for (int i = 0; i < 8; i++)
        cp16(sbase + 65536 + 32768 + (i * 256 + tid) * 16, Vsrc + (i * 256 + tid) * 4);
    asm volatile("cp.async.commit_group;");

    float o[8][4];
    #pragma unroll
    for (int nt = 0; nt < 8; nt++)
        #pragma unroll
        for (int j = 0; j < 4; j++) o[nt][j] = 0.f;
    float m0 = -1e30f, m1 = -1e30f, l0 = 0.f, l1 = 0.f;

    const int row0 = q0 + wid * 16 + (lane >> 2);
    const int c4l  = lane & 3;
    const int idx1 = (lane & 28) | (c4l >> 1);
    const int idx2 = idx1 + 2;

    for (int c = 0; c < nch; c++) {
        asm volatile("cp.async.wait_group 0;" ::: "memory");
        __syncthreads();

        if (c + 1 < nch) {
            uint32_t sb = sbase + 65536 + ((c + 1) & 1) * 65536;
            const uint32_t* Ks = Ksrc + (size_t)(c + 1) * 8192;
            const uint32_t* Vs = Vsrc + (size_t)(c + 1) * 8192;
            #pragma unroll
            for (int i = 0; i < 8; i++)
                cp16(sb + (i * 256 + tid) * 16, Ks + (i * 256 + tid) * 4);
            #pragma unroll
            for (int i = 0; i < 8; i++)
                cp16(sb + 32768 + (i * 256 + tid) * 16, Vs + (i * 256 + tid) * 4);
            asm volatile("cp.async.commit_group;");
        }

        const uint32_t* QF = atsm;
        const uint32_t* KF = atsm + 16384 + (c & 1) * 16384;
        const uint32_t* VF = KF + 8192;

        float s[8][4];
        #pragma unroll
        for (int nt = 0; nt < 8; nt++)
            #pragma unroll
            for (int j = 0; j < 4; j++) s[nt][j] = 0.f;

        #pragma unroll
        for (int ks = 0; ks < 8; ks++) {
            uint4 qh4 = *(const uint4*)&QF[(wid * 8 + ks) * 128 + lane * 4];
            uint4 ql4 = *(const uint4*)&QF[8192 + (wid * 8 + ks) * 128 + lane * 4];
            uint32_t qh[4] = {qh4.x, qh4.y, qh4.z, qh4.w};
            uint32_t ql[4] = {ql4.x, ql4.y, ql4.z, ql4.w};
            #pragma unroll
            for (int nt = 0; nt < 8; nt++) {
                uint2 kh2 = *(const uint2*)&KF[(nt * 8 + ks) * 64 + lane * 2];
                uint2 kl2 = *(const uint2*)&KF[4096 + (nt * 8 + ks) * 64 + lane * 2];
                uint32_t kh[2] = {kh2.x, kh2.y};
                uint32_t kl[2] = {kl2.x, kl2.y};
                MMA_TF32(s[nt], qh, kh);
                MMA_TF32(s[nt], ql, kh);
                MMA_TF32(s[nt], qh, kl);
            }
        }

        const int j0 = c * 64;
        if (c >= 2 * bx) {
            #pragma unroll
            for (int nt = 0; nt < 8; nt++) {
                #pragma unroll
                for (int j = 0; j < 4; j++) {
                    int col = j0 + nt * 8 + c4l * 2 + (j & 1);
                    int row = (j < 2) ? row0 : row0 + 8;
                    s[nt][j] = (col <= row) ? s[nt][j] * 0.125f : -1e30f;
                }
            }
        } else {
            #pragma unroll
            for (int nt = 0; nt < 8; nt++)
                #pragma unroll
                for (int j = 0; j < 4; j++) s[nt][j] *= 0.125f;
        }

        float mt0 = -1e30f, mt1 = -1e30f;
        #pragma unroll
        for (int nt = 0; nt < 8; nt++) {
            mt0 = fmaxf(mt0, fmaxf(s[nt][0], s[nt][1]));
            mt1 = fmaxf(mt1, fmaxf(s[nt][2], s[nt][3]));
        }
        mt0 = fmaxf(mt0, __shfl_xor_sync(0xffffffffu, mt0, 1));
        mt0 = fmaxf(mt0, __shfl_xor_sync(0xffffffffu, mt0, 2));
        mt1 = fmaxf(mt1, __shfl_xor_sync(0xffffffffu, mt1, 1));
        mt1 = fmaxf(mt1, __shfl_xor_sync(0xffffffffu, mt1, 2));

        float m0n = fmaxf(m0, mt0), m1n = fmaxf(m1, mt1);
        float a0 = __expf(m0 - m0n), a1 = __expf(m1 - m1n);
        m0 = m0n; m1 = m1n;

        float lt0 = 0.f, lt1 = 0.f;
        #pragma unroll
        for (int nt = 0; nt < 8; nt++) {
            s[nt][0] = __expf(s[nt][0] - m0n);
            s[nt][1] = __expf(s[nt][1] - m0n);
            s[nt][2] = __expf(s[nt][2] - m1n);
            s[nt][3] = __expf(s[nt][3] - m1n);
            lt0 += s[nt][0] + s[nt][1];
            lt1 += s[nt][2] + s[nt][3];
        }
        lt0 += __shfl_xor_sync(0xffffffffu, lt0, 1);
        lt0 += __shfl_xor_sync(0xffffffffu, lt0, 2);
        lt1 += __shfl_xor_sync(0xffffffffu, lt1, 1);
        lt1 += __shfl_xor_sync(0xffffffffu, lt1, 2);
        l0 = l0 * a0 + lt0;
        l1 = l1 * a1 + lt1;

        #pragma unroll
        for (int nt = 0; nt < 8; nt++) {
            o[nt][0] *= a0; o[nt][1] *= a0;
            o[nt][2] *= a1; o[nt][3] *= a1;
        }

        #pragma unroll
        for (int ks2 = 0; ks2 < 8; ks2++) {
            float v0a = __shfl_sync(0xffffffffu, s[ks2][0], idx1);
            float v0b = __shfl_sync(0xffffffffu, s[ks2][1], idx1);
            float v2a = __shfl_sync(0xffffffffu, s[ks2][0], idx2);
            float v2b = __shfl_sync(0xffffffffu, s[ks2][1], idx2);
            float v1a = __shfl_sync(0xffffffffu, s[ks2][2], idx1);
            float v1b = __shfl_sync(0xffffffffu, s[ks2][3], idx1);
            float v3a = __shfl_sync(0xffffffffu, s[ks2][2], idx2);
            float v3b = __shfl_sync(0xffffffffu, s[ks2][3], idx2);
            bool oddc = (c4l & 1);
            float af0 = oddc ? v0b : v0a;
            float af1 = oddc ? v1b : v1a;
            float af2 = oddc ? v2b : v2a;
            float af3 = oddc ? v3b : v3a;

            uint32_t pah[4], pal[4];
            cvt_hilo(af0, pah[0], pal[0]);
            cvt_hilo(af1, pah[1], pal[1]);
            cvt_hilo(af2, pah[2], pal[2]);
            cvt_hilo(af3, pah[3], pal[3]);

            #pragma unroll
            for (int nt = 0; nt < 8; nt++) {
                uint2 vh2 = *(const uint2*)&VF[(nt * 8 + ks2) * 64 + lane * 2];
                uint2 vl2 = *(const uint2*)&VF[4096 + (nt * 8 + ks2) * 64 + lane * 2];
                uint32_t vh[2] = {vh2.x, vh2.y};
                uint32_t vl[2] = {vl2.x, vl2.y};
                MMA_TF32(o[nt], pah, vh);
                MMA_TF32(o[nt], pal, vh);
                MMA_TF32(o[nt], pah, vl);
            }
        }
    }

    // epilogue: acc pairs ARE bf16-k16 A-frag reg pairs (no shuffle needed).
    // row = q0 + wid*16 + (lane>>2) + 8*rowhalf ; k = h*64 + nt*8 + (lane&3)*2
    // chunk = h*2 + (nt>>2); ks = (nt>>1)&1; reg = 2*(nt&1) + rowhalf
    float inv0 = 1.0f / l0, inv1 = 1.0f / l1;
    #pragma unroll
    for (int nt = 0; nt < 8; nt++) {
        uint32_t h0, l0b, h1, l1b;
        bf16_hilo2(o[nt][0] * inv0, o[nt][1] * inv0, h0, l0b);
        bf16_hilo2(o[nt][2] * inv1, o[nt][3] * inv1, h1, l1b);

        int chunkIdx = h * 2 + (nt >> 2);
        int ks = (nt >> 1) & 1;
        int regb = (nt & 1) * 2;
        size_t base = ((size_t)(b * 16 + bx) * 32 + chunkIdx) * 4096;
        int off = ((wid * 2 + ks) * 32 + lane) * 4 + regb;
        *(uint2*)(Ap + base + off)        = make_uint2(h0, h1);
        *(uint2*)(Ap + base + 2048 + off) = make_uint2(l0b, l1b);
    }
}

// ---------------------------------------------------------------------------
extern "C" void kernel_launch(void* const* d_in, const int* in_sizes, int n_in,
                              void* d_out, int out_size)
{
    const float* x     = (const float*)d_in[0];
    const float* w_qkv = (const float*)d_in[1];
    const float* w_out = (const float*)d_in[2];
    for (int i = 0; i < n_in; i++) {
        if      (in_sizes[i] == M_TOK * D_MODEL)       x     = (const float*)d_in[i];
        else if (in_sizes[i] == 3 * D_MODEL * D_MODEL) w_qkv = (const float*)d_in[i];
        else if (in_sizes[i] == D_MODEL * D_MODEL)     w_out = (const float*)d_in[i];
    }
    float* out = (float*)d_out;

    float *qkv = nullptr;
    uint32_t *xp = nullptr, *ap = nullptr, *vp = nullptr, *wqp = nullptr, *wop = nullptr;
    cudaGetSymbolAddress((void**)&qkv, g_qkv);
    cudaGetSymbolAddress((void**)&xp,  g_xpack);
    cudaGetSymbolAddress((void**)&ap,  g_attpack);
    cudaGetSymbolAddress((void**)&vp,  g_vpack);
    cudaGetSymbolAddress((void**)&wqp, g_wqkvp);
    cudaGetSymbolAddress((void**)&wop, g_woutp);

    static bool attr_set = false;
    if (!attr_set) {
        attr_set = true;
        cudaFuncSetAttribute(gemm_bf16,
                             cudaFuncAttributeMaxDynamicSharedMemorySize, 64 * 1024);
        cudaFuncSetAttribute(attn_tc,
                             cudaFuncAttributeMaxDynamicSharedMemorySize, 192 * 1024);
        cudaFuncSetAttribute(rope_pack,
                             cudaFuncAttributeMaxDynamicSharedMemorySize, 112 * 1024);
    }

    // 0) trig table + bf16 GEMM operand packs
    trig_kernel<<<(SEQ * 32) / 256, 256>>>();
    pack_a_bf16<<<(M_TOK * 1024 / 2) / 256, 256>>>(x, xp);
    pack_b_bf16<<<(3 * D_MODEL * 1024 / 2) / 256, 256>>>(w_qkv, wqp);
    pack_b_bf16<<<(D_MODEL * 1024 / 2) / 256, 256>>>(w_out, wop);

    // 1) QKV projection (bf16 3-pass) -> g_qkv
    gemm_bf16<<<dim3(3 * D_MODEL / 128, M_TOK / 128), 256, 64 * 1024>>>(
        xp, wqp, qkv, M_TOK, 3 * D_MODEL, D_MODEL);

    // 2) Fused rope + tf32 Q/K/V fragment pack
    rope_pack<<<dim3(16, 64), 256, 112 * 1024>>>(xp, ap, vp);

    // 3) Tensor-core flash attention; epilogue emits bf16 out-proj A-frags
    attn_tc<<<dim3(SEQ / 128, BATCH * N_HEADS), 256, 192 * 1024>>>(
        xp, ap, vp, (uint32_t*)qkv);

    // 4) Output projection (bf16 3-pass, reads A-frags from g_qkv)
    gemm_bf16<<<dim3(D_MODEL / 128, M_TOK / 128), 256, 64 * 1024>>>(
        (const uint32_t*)qkv, wop, out, M_TOK, D_MODEL, D_MODEL);
}